// round 10
// baseline (speedup 1.0000x reference)
#include <cuda_runtime.h>
#include <math.h>
#include <stdint.h>

#define NROWS 100352

__device__ float g_q[(size_t)24576*1568];   // [B*H, 49, 32], pre-scaled, tf32-rounded
__device__ float g_k[(size_t)24576*1568];
__device__ float g_v[(size_t)24576*1568];
__device__ float g_hid[(size_t)NROWS*384];  // tf32-rounded hidden
__device__ float g_wq[1152*384];            // tf32-rounded w_qkv
__device__ float g_wo[384*384];             // tf32-rounded w_out
__device__ int   g_ridx[2401];              // rel-pos index * 12

__device__ __forceinline__ uint32_t smem_u32(const void* p) {
    uint32_t a;
    asm("{ .reg .u64 t; cvta.to.shared.u64 t, %1; cvt.u32.u64 %0, t; }" : "=r"(a) : "l"(p));
    return a;
}
__device__ __forceinline__ uint32_t f2tf(float x) {
    uint32_t r; asm("cvt.rna.tf32.f32 %0, %1;" : "=r"(r) : "f"(x)); return r;
}
__device__ __forceinline__ float tf32f(float x) { return __uint_as_float(f2tf(x)); }
__device__ __forceinline__ void mma8(float* c, const uint32_t* a, uint32_t b0, uint32_t b1) {
    asm volatile("mma.sync.aligned.m16n8k8.row.col.f32.tf32.tf32.f32 "
        "{%0,%1,%2,%3}, {%4,%5,%6,%7}, {%8,%9}, {%0,%1,%2,%3};"
        : "+f"(c[0]), "+f"(c[1]), "+f"(c[2]), "+f"(c[3])
        : "r"(a[0]), "r"(a[1]), "r"(a[2]), "r"(a[3]), "r"(b0), "r"(b1));
}
__device__ __forceinline__ void ldsm4(uint32_t* r, uint32_t a) {
    asm volatile("ldmatrix.sync.aligned.m8n8.x4.shared.b16 {%0,%1,%2,%3}, [%4];"
        : "=r"(r[0]), "=r"(r[1]), "=r"(r[2]), "=r"(r[3]) : "r"(a));
}
__device__ __forceinline__ void ldsm2(uint32_t* r, uint32_t a) {
    asm volatile("ldmatrix.sync.aligned.m8n8.x2.shared.b16 {%0,%1}, [%2];"
        : "=r"(r[0]), "=r"(r[1]) : "r"(a));
}
__device__ __forceinline__ void cp16(uint32_t s, const float* g) {
    asm volatile("cp.async.cg.shared.global [%0], [%1], 16;" :: "r"(s), "l"(g));
}

// ---------------------------------------------------------------------------
__global__ void round_kernel(const float4* __restrict__ src, float4* __restrict__ dst, int n4) {
    int i = blockIdx.x * blockDim.x + threadIdx.x;
    if (i < n4) {
        float4 v = src[i];
        v.x = tf32f(v.x); v.y = tf32f(v.y); v.z = tf32f(v.z); v.w = tf32f(v.w);
        dst[i] = v;
    }
}
__global__ void ridx_kernel() {
    int e = blockIdx.x * blockDim.x + threadIdx.x;
    if (e < 2401) {
        int i = e / 49, j = e - i * 49;
        int yi = i / 7, xi = i - yi * 7, yj = j / 7, xj = j - yj * 7;
        g_ridx[e] = ((yi - yj + 6) * 13 + (xi - xj + 6)) * 12;
    }
}

// ===========================================================================
// TF32 GEMM for QKV (unchanged from R9)
// ===========================================================================
__device__ __forceinline__ void gemm_tf32(const float* __restrict__ A,
                                          const float* __restrict__ W,
                                          int bm, int bn, float acc[4][4][4])
{
    extern __shared__ float sm[];
    const int tid = threadIdx.x;
    const int l = tid & 31, l7 = l & 7;
    const int wm = (tid >> 5) >> 2, wn = (tid >> 5) & 3;

    const int prow = tid >> 1, pc = (tid & 1) * 16;
    const float* ga = A + (size_t)(bm + prow) * 384 + pc;
    const float* gb = W + (size_t)(bn + prow) * 384 + pc;
    const uint32_t swz = (uint32_t)((prow & 7) << 2);
    const uint32_t sa0 = smem_u32(sm) + (uint32_t)prow * 128;
    const uint32_t sb0 = sa0 + 49152;

#pragma unroll
    for (int mi = 0; mi < 4; mi++)
#pragma unroll
        for (int nj = 0; nj < 4; nj++)
#pragma unroll
            for (int q = 0; q < 4; q++) acc[mi][nj][q] = 0.f;

#define ISSUE(KT) do {                                                        \
    uint32_t off = (uint32_t)((KT) % 3) * 16384;                              \
    const float* pa = ga + (KT) * 32;                                         \
    const float* pb = gb + (KT) * 32;                                         \
    _Pragma("unroll")                                                         \
    for (int u = 0; u < 4; u++) {                                             \
        uint32_t c = ((uint32_t)(pc + 4 * u) ^ swz) * 4;                      \
        cp16(sa0 + off + c, pa + 4 * u);                                      \
        cp16(sb0 + off + c, pb + 4 * u);                                      \
    }                                                                         \
    asm volatile("cp.async.commit_group;" ::: "memory");                      \
} while (0)

    ISSUE(0); ISSUE(1);

    const int ah = (l >> 3) & 1, bh2 = l >> 4;
    uint32_t a_rb[4], b_rb[2];
#pragma unroll
    for (int mi = 0; mi < 4; mi++)
        a_rb[mi] = (uint32_t)((wm * 64 + mi * 16 + l7 + ah * 8) * 128);
#pragma unroll
    for (int p = 0; p < 2; p++)
        b_rb[p] = (uint32_t)((wn * 32 + p * 16 + l7 + bh2 * 8) * 128);
    const uint32_t smbase = smem_u32(sm);

    for (int kt = 0; kt < 12; kt++) {
        if (kt < 11) asm volatile("cp.async.wait_group 1;" ::: "memory");
        else         asm volatile("cp.async.wait_group 0;" ::: "memory");
        __syncthreads();
        if (kt < 10) ISSUE(kt + 2);

        const uint32_t bA = smbase + (uint32_t)(kt % 3) * 16384;
        const uint32_t bB = bA + 49152;
#pragma unroll
        for (int kc = 0; kc < 4; kc++) {
            const uint32_t uA = (uint32_t)(((2 * kc + bh2) ^ l7) << 4);
            const uint32_t uB = (uint32_t)(((2 * kc + ah) ^ l7) << 4);
            uint32_t af[4][4], b0[4], b1[4];
#pragma unroll
            for (int mi = 0; mi < 4; mi++) ldsm4(af[mi], bA + a_rb[mi] + uA);
            ldsm4(b0, bB + b_rb[0] + uB);
            ldsm4(b1, bB + b_rb[1] + uB);
#pragma unroll
            for (int mi = 0; mi < 4; mi++) {
                mma8(acc[mi][0], af[mi], b0[0], b0[1]);
                mma8(acc[mi][1], af[mi], b0[2], b0[3]);
                mma8(acc[mi][2], af[mi], b1[0], b1[1]);
                mma8(acc[mi][3], af[mi], b1[2], b1[3]);
            }
        }
    }
#undef ISSUE
}

// ---------------------------------------------------------------------------
__global__ void __launch_bounds__(256, 2)
mma_qkv_kernel(const float* __restrict__ bias)
{
    int tid = threadIdx.x;
    int bm = blockIdx.y * 128, bn = blockIdx.x * 128;
    float acc[4][4][4];
    gemm_tf32(g_hid, g_wq, bm, bn, acc);

    int l = tid & 31;
    int wm = (tid >> 5) >> 2, wn = (tid >> 5) & 3;
    int part = bn / 384;
    int h = ((bn % 384) + wn * 32) >> 5;
    const float scl = (part == 0) ? 0.17677669529663687f : 1.0f;
    float* base = (part == 0) ? g_q : (part == 1) ? g_k : g_v;

#pragma unroll
    for (int mi = 0; mi < 4; mi++)
#pragma unroll
        for (int nj = 0; nj < 4; nj++) {
            int n = bn + wn * 32 + nj * 8 + (l & 3) * 2;
            int d = nj * 8 + (l & 3) * 2;
            float b0 = bias[n], b1 = bias[n + 1];
#pragma unroll
            for (int rh = 0; rh < 2; rh++) {
                int row = bm + wm * 64 + mi * 16 + (l >> 2) + rh * 8;
                int bb = row / 49, ss = row - bb * 49;
                size_t o = (((size_t)(bb * 12 + h) * 49 + ss) << 5) + d;
                *(float2*)&base[o] =
                    make_float2(tf32f((acc[mi][nj][rh*2] + b0) * scl),
                                tf32f((acc[mi][nj][rh*2+1] + b1) * scl));
            }
        }
}

// ===========================================================================
// Fused attention + output projection. One CTA per window b. 256 threads.
// Phase A: two 4-warp halves each process 6 heads -> att_s[64][396] in smem.
// Phase B: C[49,384] = att_s @ Wo^T + b_out, Wo streamed via cp.async.
// smem floats: att_s 25344 | mask 2404 | half0 10400 | half1 10400
//              (phase B overlays [25344, 25344+24576) with Wo dbl buffer)
// ===========================================================================
__global__ void __launch_bounds__(256)
fused_attn_out_kernel(const float* __restrict__ mask,
                      const float* __restrict__ table,
                      const float* __restrict__ obias,
                      float* __restrict__ C)
{
    extern __shared__ float sm[];
    float* att_s  = sm;                 // 64 x 396
    float* mask_s = sm + 25344;         // 2401 (+pad)
    const int tid = threadIdx.x;
    const int w = tid >> 5, l = tid & 31, g = l >> 2, t = l & 3;
    const int l7 = l & 7, ah = (l >> 3) & 1, bh2 = l >> 4;
    const int hw = tid >> 7, w4 = w & 3, tid128 = tid & 127;
    const int b = blockIdx.x;

    float* half_b = sm + 27748 + hw * 10400;
    float* qs = half_b;            // 64x36
    float* ks = half_b + 2304;     // 56x36
    float* vs = half_b + 4320;     // 56x40
    float* amb = half_b + 6560;    // 64x60
    const uint32_t qsb = smem_u32(qs), ksb = smem_u32(ks), ambb = smem_u32(amb);
    const uint32_t attb = smem_u32(att_s);

    for (int e = tid; e < 2401; e += 256) mask_s[e] = mask[(size_t)b * 2401 + e];
    __syncthreads();

    const uint32_t qrow = (uint32_t)((w4 * 16 + l7 + ah * 8) * 144);
    uint32_t krow[3];
#pragma unroll
    for (int p = 0; p < 3; p++) krow[p] = (uint32_t)((p * 16 + l7 + bh2 * 8) * 144);
    const uint32_t krow6 = (uint32_t)((48 + l7) * 144);
    const uint32_t prow = (uint32_t)((w4 * 16 + l7 + ah * 8) * 240);
    const int rA = w4 * 16 + g;

    for (int hp = 0; hp < 6; hp++) {
        const int head = 2 * hp + hw;
        const size_t bh = (size_t)b * 12 + head;
        const float4* qg = (const float4*)(g_q + bh * 1568);
        const float4* kg = (const float4*)(g_k + bh * 1568);
        const float4* vg = (const float4*)(g_v + bh * 1568);
        for (int e = tid128; e < 392; e += 128) {
            int i = e >> 3, c = (e & 7) * 4;
            *(float4*)&qs[i * 36 + c] = qg[e];
            *(float4*)&ks[i * 36 + c] = kg[e];
            *(float4*)&vs[i * 40 + c] = vg[e];
        }
        for (int e = tid128; e < 280; e += 128) vs[1960 + e] = 0.f;
        for (int e = tid128; e < 2401; e += 128) {
            int i = e / 49, j = e - i * 49;
            amb[i * 60 + j] = mask_s[e] + table[g_ridx[e] + head];
        }
        __syncthreads();

        // QK^T
        float s[7][4];
#pragma unroll
        for (int T = 0; T < 7; T++) { s[T][0]=0.f; s[T][1]=0.f; s[T][2]=0.f; s[T][3]=0.f; }
#pragma unroll
        for (int kc = 0; kc < 4; kc++) {
            uint32_t a[4];
            ldsm4(a, qsb + qrow + (uint32_t)((2 * kc + bh2) << 4));
            uint32_t uB = (uint32_t)((2 * kc + ah) << 4);
#pragma unroll
            for (int p = 0; p < 3; p++) {
                uint32_t kb[4];
                ldsm4(kb, ksb + krow[p] + uB);
                mma8(s[2*p],   a, kb[0], kb[1]);
                mma8(s[2*p+1], a, kb[2], kb[3]);
            }
            uint32_t k2[2];
            ldsm2(k2, ksb + krow6 + uB);
            mma8(s[6], a, k2[0], k2[1]);
        }
#pragma unroll
        for (int T = 0; T < 7; T++) {
            int j0 = T * 8 + 2 * t;
            float2 m0 = *(const float2*)&amb[rA * 60 + j0];
            float2 m1 = *(const float2*)&amb[(rA + 8) * 60 + j0];
            s[T][0] = (j0 < 49)     ? s[T][0] + m0.x : -1e30f;
            s[T][1] = (j0 + 1 < 49) ? s[T][1] + m0.y : -1e30f;
            s[T][2] = (j0 < 49)     ? s[T][2] + m1.x : -1e30f;
            s[T][3] = (j0 + 1 < 49) ? s[T][3] + m1.y : -1e30f;
        }
        float mA = -1e30f, mB = -1e30f;
#pragma unroll
        for (int T = 0; T < 7; T++) {
            mA = fmaxf(mA, fmaxf(s[T][0], s[T][1]));
            mB = fmaxf(mB, fmaxf(s[T][2], s[T][3]));
        }
        mA = fmaxf(mA, __shfl_xor_sync(~0u, mA, 1)); mA = fmaxf(mA, __shfl_xor_sync(~0u, mA, 2));
        mB = fmaxf(mB, __shfl_xor_sync(~0u, mB, 1)); mB = fmaxf(mB, __shfl_xor_sync(~0u, mB, 2));
        float dA = 0.f, dB = 0.f;
#pragma unroll
        for (int T = 0; T < 7; T++) {
            s[T][0] = __expf(s[T][0] - mA); s[T][1] = __expf(s[T][1] - mA);
            s[T][2] = __expf(s[T][2] - mB); s[T][3] = __expf(s[T][3] - mB);
            dA += s[T][0] + s[T][1]; dB += s[T][2] + s[T][3];
        }
        dA += __shfl_xor_sync(~0u, dA, 1); dA += __shfl_xor_sync(~0u, dA, 2);
        dB += __shfl_xor_sync(~0u, dB, 1); dB += __shfl_xor_sync(~0u, dB, 2);
        float iA = 1.f / dA, iB = 1.f / dB;
#pragma unroll
        for (int T = 0; T < 7; T++) {
            int j0 = T * 8 + 2 * t;
            *(float2*)&amb[rA * 60 + j0] =
                make_float2(tf32f(s[T][0] * iA), tf32f(s[T][1] * iA));
            *(float2*)&amb[(rA + 8) * 60 + j0] =
                make_float2(tf32f(s[T][2] * iB), tf32f(s[T][3] * iB));
        }
        __syncwarp();

        // PV
        float o[4][4];
#pragma unroll
        for (int nj = 0; nj < 4; nj++) { o[nj][0]=0.f; o[nj][1]=0.f; o[nj][2]=0.f; o[nj][3]=0.f; }
#pragma unroll
        for (int kc = 0; kc < 7; kc++) {
            uint32_t a[4];
            ldsm4(a, ambb + prow + (uint32_t)((2 * kc + bh2) << 4));
            int c = kc * 8 + t;
#pragma unroll
            for (int nj = 0; nj < 4; nj++)
                mma8(o[nj], a, __float_as_uint(vs[c * 40 + nj * 8 + g]),
                     __float_as_uint(vs[(c + 4) * 40 + nj * 8 + g]));
        }
        float* ap = att_s + head * 32;
#pragma unroll
        for (int nj = 0; nj < 4; nj++) {
            int d = nj * 8 + 2 * t;
            *(float2*)&ap[rA * 396 + d] = make_float2(tf32f(o[nj][0]), tf32f(o[nj][1]));
            *(float2*)&ap[(rA + 8) * 396 + d] = make_float2(tf32f(o[nj][2]), tf32f(o[nj][3]));
        }
        __syncthreads();
    }

    // ---- Phase B: out projection from att_s ----
    const uint32_t wob = smem_u32(sm + 25344);
    const int wm = w >> 2, wn = w & 3;

#define WOLOAD(KT) do {                                                       \
    uint32_t bb = wob + (uint32_t)(((KT) & 1) * 49152);                       \
    const float* gp = g_wo + (KT) * 32;                                       \
    _Pragma("unroll")                                                         \
    for (int i = 0; i < 12; i++) {                                            \
        int u = i * 256 + tid;                                                \
        int row = u >> 3, un = u & 7;                                         \
        cp16(bb + (uint32_t)(row * 128 + ((un ^ (row & 7)) << 4)),            \
             gp + row * 384 + un * 4);                                        \
    }                                                                         \
    asm volatile("cp.async.commit_group;" ::: "memory");                      \
} while (0)

    float acc[2][12][4];
#pragma unroll
    for (int mi = 0; mi < 2; mi++)
#pragma unroll
        for (int nj = 0; nj < 12; nj++)
#pragma unroll
            for (int q = 0; q < 4; q++) acc[mi][nj][q] = 0.f;

    uint32_t a_base[2];
#pragma unroll
    for (int mi = 0; mi < 2; mi++)
        a_base[mi] = (uint32_t)((wm * 32 + mi * 16 + l7 + ah * 8) * 1584);
    uint32_t b_off[6];
#pragma unroll
    for (int nt = 0; nt < 6; nt++)
        b_off[nt] = (uint32_t)((wn * 96 + nt * 16 + l7 + bh2 * 8) * 128);

    WOLOAD(0);
    for (int kt = 0; kt < 12; kt++) {
        if (kt < 11) {
            WOLOAD(kt + 1);
            asm volatile("cp.async.wait_group 1;" ::: "memory");
        } else {
            asm volatile("cp.async.wait_group 0;" ::: "memory");
        }
        __syncthreads();
        const uint32_t bufb = wob + (uint32_t)((kt & 1) * 49152);
#pragma unroll
        for (int kc = 0; kc < 4; kc++) {
            const uint32_t uA = (uint32_t)((2 * (kt * 4 + kc) + bh2) << 4);
            const uint32_t uB = (uint32_t)((((2 * kc + ah) ^ l7)) << 4);
            uint32_t af[2][4];
            ldsm4(af[0], attb + a_base[0] + uA);
            ldsm4(af[1], attb + a_base[1] + uA);
#pragma unroll
            for (int nt = 0; nt < 6; nt++) {
                uint32_t bf[4];
                ldsm4(bf, bufb + b_off[nt] + uB);
                mma8(acc[0][2*nt],   af[0], bf[0], bf[1]);
                mma8(acc[0][2*nt+1], af[0], bf[2], bf[3]);
                mma8(acc[1][2*nt],   af[1], bf[0], bf[1]);
                mma8(acc[1][2*nt+1], af[1], bf[2], bf[3]);
            }
        }
        __syncthreads();
    }
#undef WOLOAD

#pragma unroll
    for (int mi = 0; mi < 2; mi++)
#pragma unroll
        for (int nj = 0; nj < 12; nj++) {
            int n = wn * 96 + nj * 8 + 2 * t;
            float b0 = obias[n], b1 = obias[n + 1];
#pragma unroll
            for (int rh = 0; rh < 2; rh++) {
                int r = wm * 32 + mi * 16 + g + rh * 8;
                if (r < 49)
                    *(float2*)&C[(size_t)(b * 49 + r) * 384 + n] =
                        make_float2(acc[mi][nj][rh*2] + b0, acc[mi][nj][rh*2+1] + b1);
            }
        }
}

// ---------------------------------------------------------------------------
extern "C" void kernel_launch(void* const* d_in, const int* in_sizes, int n_in,
                              void* d_out, int out_size)
{
    const float* hidden = (const float*)d_in[0];
    const float* mask   = (const float*)d_in[1];
    const float* w_qkv  = (const float*)d_in[2];
    const float* b_qkv  = (const float*)d_in[3];
    const float* w_out  = (const float*)d_in[4];
    const float* b_out  = (const float*)d_in[5];
    const float* table  = (const float*)d_in[6];
    float* out = (float*)d_out;

    float* hid_p; cudaGetSymbolAddress((void**)&hid_p, g_hid);
    float* wq_p;  cudaGetSymbolAddress((void**)&wq_p,  g_wq);
    float* wo_p;  cudaGetSymbolAddress((void**)&wo_p,  g_wo);

    round_kernel<<<(NROWS*384/4 + 255)/256, 256>>>((const float4*)hidden, (float4*)hid_p, NROWS*384/4);
    round_kernel<<<(1152*384/4 + 255)/256, 256>>>((const float4*)w_qkv, (float4*)wq_p, 1152*384/4);
    round_kernel<<<(384*384/4 + 255)/256, 256>>>((const float4*)w_out, (float4*)wo_p, 384*384/4);
    ridx_kernel<<<10, 256>>>();

    const int SMEM_G = 98304;
    const int SMEM_F = 199680;  // 49920 floats
    cudaFuncSetAttribute(mma_qkv_kernel, cudaFuncAttributeMaxDynamicSharedMemorySize, SMEM_G);
    cudaFuncSetAttribute(fused_attn_out_kernel, cudaFuncAttributeMaxDynamicSharedMemorySize, SMEM_F);

    mma_qkv_kernel<<<dim3(9, 784), 256, SMEM_G>>>(b_qkv);
    fused_attn_out_kernel<<<2048, 256, SMEM_F>>>(mask, table, b_out, out);
}

// round 11
// speedup vs baseline: 1.1422x; 1.1422x over previous
#include <cuda_runtime.h>
#include <math.h>
#include <stdint.h>

#define NROWS 100352

__device__ float g_q[(size_t)24576*1568];   // [B*H, 49, 32], pre-scaled, tf32-rounded
__device__ float g_k[(size_t)24576*1568];
__device__ float g_v[(size_t)24576*1568];
__device__ float g_att[(size_t)NROWS*384];  // tf32-rounded
__device__ float g_hid[(size_t)NROWS*384];  // tf32-rounded hidden
__device__ float g_wq[1152*384];            // tf32-rounded w_qkv
__device__ float g_wo[384*384];             // tf32-rounded w_out
__device__ int   g_pack[2401];              // (i*60+j)<<16 | ridx*12

__device__ __forceinline__ uint32_t smem_u32(const void* p) {
    uint32_t a;
    asm("{ .reg .u64 t; cvta.to.shared.u64 t, %1; cvt.u32.u64 %0, t; }" : "=r"(a) : "l"(p));
    return a;
}
__device__ __forceinline__ uint32_t f2tf(float x) {
    uint32_t r; asm("cvt.rna.tf32.f32 %0, %1;" : "=r"(r) : "f"(x)); return r;
}
__device__ __forceinline__ float tf32f(float x) { return __uint_as_float(f2tf(x)); }
__device__ __forceinline__ void mma8(float* c, const uint32_t* a, uint32_t b0, uint32_t b1) {
    asm volatile("mma.sync.aligned.m16n8k8.row.col.f32.tf32.tf32.f32 "
        "{%0,%1,%2,%3}, {%4,%5,%6,%7}, {%8,%9}, {%0,%1,%2,%3};"
        : "+f"(c[0]), "+f"(c[1]), "+f"(c[2]), "+f"(c[3])
        : "r"(a[0]), "r"(a[1]), "r"(a[2]), "r"(a[3]), "r"(b0), "r"(b1));
}
__device__ __forceinline__ void ldsm4(uint32_t* r, uint32_t a) {
    asm volatile("ldmatrix.sync.aligned.m8n8.x4.shared.b16 {%0,%1,%2,%3}, [%4];"
        : "=r"(r[0]), "=r"(r[1]), "=r"(r[2]), "=r"(r[3]) : "r"(a));
}
__device__ __forceinline__ void ldsm2(uint32_t* r, uint32_t a) {
    asm volatile("ldmatrix.sync.aligned.m8n8.x2.shared.b16 {%0,%1}, [%2];"
        : "=r"(r[0]), "=r"(r[1]) : "r"(a));
}
__device__ __forceinline__ void cp16(uint32_t s, const float* g) {
    asm volatile("cp.async.cg.shared.global [%0], [%1], 16;" :: "r"(s), "l"(g));
}

// ---------------------------------------------------------------------------
// Single prep kernel: tf32-round hidden / w_qkv / w_out + build pack table.
// ---------------------------------------------------------------------------
#define NH4 9633792   // NROWS*384/4
#define NQ4 110592    // 1152*384/4
#define NO4 36864     // 384*384/4

__global__ void prep_kernel(const float4* __restrict__ hid, const float4* __restrict__ wq,
                            const float4* __restrict__ wo, float4* __restrict__ dh,
                            float4* __restrict__ dwq, float4* __restrict__ dwo)
{
    int i = blockIdx.x * blockDim.x + threadIdx.x;
    const float4* s; float4* d; int k;
    if (i < NH4)            { s = hid; d = dh;  k = i; }
    else if (i < NH4 + NQ4) { s = wq;  d = dwq; k = i - NH4; }
    else if (i < NH4 + NQ4 + NO4) { s = wo; d = dwo; k = i - NH4 - NQ4; }
    else return;
    float4 v = s[k];
    v.x = tf32f(v.x); v.y = tf32f(v.y); v.z = tf32f(v.z); v.w = tf32f(v.w);
    d[k] = v;
    if (i < 2401) {
        int r = i / 49, j = i - r * 49;
        int yi = r / 7, xi = r - yi * 7, yj = j / 7, xj = j - yj * 7;
        int ridx = (yi - yj + 6) * 13 + (xi - xj + 6);
        g_pack[i] = ((r * 60 + j) << 16) | (ridx * 12);
    }
}

// ===========================================================================
// TF32 GEMM: C[128x128] of A[M,384] @ W[N,384]^T; inputs pre-rounded.
// 8 warps, BK=32, 3-stage cp.async, XOR-swizzled tiles, ldmatrix frag loads.
// ===========================================================================
__device__ __forceinline__ void gemm_tf32(const float* __restrict__ A,
                                          const float* __restrict__ W,
                                          int bm, int bn, float acc[4][4][4])
{
    extern __shared__ float sm[];
    const int tid = threadIdx.x;
    const int l = tid & 31, l7 = l & 7;
    const int wm = (tid >> 5) >> 2, wn = (tid >> 5) & 3;

    const int prow = tid >> 1, pc = (tid & 1) * 16;
    const float* ga = A + (size_t)(bm + prow) * 384 + pc;
    const float* gb = W + (size_t)(bn + prow) * 384 + pc;
    const uint32_t swz = (uint32_t)((prow & 7) << 2);
    const uint32_t sa0 = smem_u32(sm) + (uint32_t)prow * 128;
    const uint32_t sb0 = sa0 + 49152;

#pragma unroll
    for (int mi = 0; mi < 4; mi++)
#pragma unroll
        for (int nj = 0; nj < 4; nj++)
#pragma unroll
            for (int q = 0; q < 4; q++) acc[mi][nj][q] = 0.f;

#define ISSUE(KT) do {                                                        \
    uint32_t off = (uint32_t)((KT) % 3) * 16384;                              \
    const float* pa = ga + (KT) * 32;                                         \
    const float* pb = gb + (KT) * 32;                                         \
    _Pragma("unroll")                                                         \
    for (int u = 0; u < 4; u++) {                                             \
        uint32_t c = ((uint32_t)(pc + 4 * u) ^ swz) * 4;                      \
        cp16(sa0 + off + c, pa + 4 * u);                                      \
        cp16(sb0 + off + c, pb + 4 * u);                                      \
    }                                                                         \
    asm volatile("cp.async.commit_group;" ::: "memory");                      \
} while (0)

    ISSUE(0); ISSUE(1);

    const int ah = (l >> 3) & 1, bh2 = l >> 4;
    uint32_t a_rb[4], b_rb[2];
#pragma unroll
    for (int mi = 0; mi < 4; mi++)
        a_rb[mi] = (uint32_t)((wm * 64 + mi * 16 + l7 + ah * 8) * 128);
#pragma unroll
    for (int p = 0; p < 2; p++)
        b_rb[p] = (uint32_t)((wn * 32 + p * 16 + l7 + bh2 * 8) * 128);
    const uint32_t smbase = smem_u32(sm);

    for (int kt = 0; kt < 12; kt++) {
        if (kt < 11) asm volatile("cp.async.wait_group 1;" ::: "memory");
        else         asm volatile("cp.async.wait_group 0;" ::: "memory");
        __syncthreads();
        if (kt < 10) ISSUE(kt + 2);

        const uint32_t bA = smbase + (uint32_t)(kt % 3) * 16384;
        const uint32_t bB = bA + 49152;
#pragma unroll
        for (int kc = 0; kc < 4; kc++) {
            const uint32_t uA = (uint32_t)(((2 * kc + bh2) ^ l7) << 4);
            const uint32_t uB = (uint32_t)(((2 * kc + ah) ^ l7) << 4);
            uint32_t af[4][4], b0[4], b1[4];
#pragma unroll
            for (int mi = 0; mi < 4; mi++) ldsm4(af[mi], bA + a_rb[mi] + uA);
            ldsm4(b0, bB + b_rb[0] + uB);
            ldsm4(b1, bB + b_rb[1] + uB);
#pragma unroll
            for (int mi = 0; mi < 4; mi++) {
                mma8(acc[mi][0], af[mi], b0[0], b0[1]);
                mma8(acc[mi][1], af[mi], b0[2], b0[3]);
                mma8(acc[mi][2], af[mi], b1[0], b1[1]);
                mma8(acc[mi][3], af[mi], b1[2], b1[3]);
            }
        }
    }
#undef ISSUE
}

// ---------------------------------------------------------------------------
__global__ void __launch_bounds__(256, 2)
mma_qkv_kernel(const float* __restrict__ bias)
{
    int tid = threadIdx.x;
    int bm = blockIdx.y * 128, bn = blockIdx.x * 128;
    float acc[4][4][4];
    gemm_tf32(g_hid, g_wq, bm, bn, acc);

    int l = tid & 31;
    int wm = (tid >> 5) >> 2, wn = (tid >> 5) & 3;
    int part = bn / 384;
    int h = ((bn % 384) + wn * 32) >> 5;
    const float scl = (part == 0) ? 0.17677669529663687f : 1.0f;
    float* base = (part == 0) ? g_q : (part == 1) ? g_k : g_v;

#pragma unroll
    for (int mi = 0; mi < 4; mi++)
#pragma unroll
        for (int nj = 0; nj < 4; nj++) {
            int n = bn + wn * 32 + nj * 8 + (l & 3) * 2;
            int d = nj * 8 + (l & 3) * 2;
            float b0 = bias[n], b1 = bias[n + 1];
#pragma unroll
            for (int rh = 0; rh < 2; rh++) {
                int row = bm + wm * 64 + mi * 16 + (l >> 2) + rh * 8;
                int bb = row / 49, ss = row - bb * 49;
                size_t o = (((size_t)(bb * 12 + h) * 49 + ss) << 5) + d;
                *(float2*)&base[o] =
                    make_float2(tf32f((acc[mi][nj][rh*2] + b0) * scl),
                                tf32f((acc[mi][nj][rh*2+1] + b1) * scl));
            }
        }
}

// ---------------------------------------------------------------------------
__global__ void __launch_bounds__(256, 2)
mma_out_kernel(const float* __restrict__ bias, float* __restrict__ C)
{
    int tid = threadIdx.x;
    int bm = blockIdx.y * 128, bn = blockIdx.x * 128;
    float acc[4][4][4];
    gemm_tf32(g_att, g_wo, bm, bn, acc);

    int l = tid & 31;
    int wm = (tid >> 5) >> 2, wn = (tid >> 5) & 3;
#pragma unroll
    for (int mi = 0; mi < 4; mi++)
#pragma unroll
        for (int nj = 0; nj < 4; nj++) {
            int n = bn + wn * 32 + nj * 8 + (l & 3) * 2;
            float b0 = bias[n], b1 = bias[n + 1];
#pragma unroll
            for (int rh = 0; rh < 2; rh++) {
                int row = bm + wm * 64 + mi * 16 + (l >> 2) + rh * 8;
                *(float2*)&C[(size_t)row * 384 + n] =
                    make_float2(acc[mi][nj][rh*2] + b0, acc[mi][nj][rh*2+1] + b1);
            }
        }
}

// ---------------------------------------------------------------------------
// Attention: one CTA per (b,h). ldmatrix fragment loads for Q/K/P.
// ---------------------------------------------------------------------------
__global__ void __launch_bounds__(128)
attn_kernel(const float* __restrict__ mask, const float* __restrict__ table)
{
    __shared__ float qs[64 * 36];
    __shared__ float ks[56 * 36];
    __shared__ float vs[56 * 40];
    __shared__ float amb[64 * 60];  // bias+mask, then P (tf32-rounded)

    int bh = blockIdx.x;
    int b = bh / 12, h = bh - b * 12;
    int tid = threadIdx.x, w = tid >> 5, l = tid & 31, g = l >> 2, t = l & 3;
    const int l7 = l & 7, ah = (l >> 3) & 1, bh2 = l >> 4;

    const float4* qg = (const float4*)(g_q + (size_t)bh * 1568);
    const float4* kg = (const float4*)(g_k + (size_t)bh * 1568);
    const float4* vg = (const float4*)(g_v + (size_t)bh * 1568);
    for (int e = tid; e < 392; e += 128) {
        int i = e >> 3, c = (e & 7) * 4;
        *(float4*)&qs[i * 36 + c] = qg[e];
        *(float4*)&ks[i * 36 + c] = kg[e];
        *(float4*)&vs[i * 40 + c] = vg[e];
    }
    for (int e = tid; e < 280; e += 128) vs[1960 + e] = 0.f;
    const float* mrow = mask + (size_t)b * 2401;
    for (int e = tid; e < 2401; e += 128) {
        int pk = g_pack[e];
        amb[pk >> 16] = mrow[e] + table[(pk & 0xFFFF) + h];
    }
    __syncthreads();

    const uint32_t qsb = smem_u32(qs), ksb = smem_u32(ks), ambb = smem_u32(amb);
    const uint32_t qrow = (uint32_t)((w * 16 + l7 + ah * 8) * 144);
    uint32_t krow[3];
#pragma unroll
    for (int p = 0; p < 3; p++)
        krow[p] = (uint32_t)((p * 16 + l7 + bh2 * 8) * 144);
    const uint32_t krow6 = (uint32_t)((48 + l7) * 144);

    // QK^T
    float s[7][4];
#pragma unroll
    for (int T = 0; T < 7; T++) { s[T][0]=0.f; s[T][1]=0.f; s[T][2]=0.f; s[T][3]=0.f; }
    const int rA = w * 16 + g;
#pragma unroll
    for (int kc = 0; kc < 4; kc++) {
        uint32_t a[4];
        ldsm4(a, qsb + qrow + (uint32_t)((2 * kc + bh2) << 4));
        uint32_t uB = (uint32_t)((2 * kc + ah) << 4);
#pragma unroll
        for (int p = 0; p < 3; p++) {
            uint32_t kb[4];
            ldsm4(kb, ksb + krow[p] + uB);
            mma8(s[2*p],   a, kb[0], kb[1]);
            mma8(s[2*p+1], a, kb[2], kb[3]);
        }
        uint32_t k2[2];
        ldsm2(k2, ksb + krow6 + uB);
        mma8(s[6], a, k2[0], k2[1]);
    }
    // + bias + mask, j>=49 -> -inf
#pragma unroll
    for (int T = 0; T < 7; T++) {
        int j0 = T * 8 + 2 * t;
        float2 m0 = *(const float2*)&amb[rA * 60 + j0];
        float2 m1 = *(const float2*)&amb[(rA + 8) * 60 + j0];
        s[T][0] = (j0 < 49)     ? s[T][0] + m0.x : -1e30f;
        s[T][1] = (j0 + 1 < 49) ? s[T][1] + m0.y : -1e30f;
        s[T][2] = (j0 < 49)     ? s[T][2] + m1.x : -1e30f;
        s[T][3] = (j0 + 1 < 49) ? s[T][3] + m1.y : -1e30f;
    }
    // softmax (rows rA, rA+8)
    float mA = -1e30f, mB = -1e30f;
#pragma unroll
    for (int T = 0; T < 7; T++) {
        mA = fmaxf(mA, fmaxf(s[T][0], s[T][1]));
        mB = fmaxf(mB, fmaxf(s[T][2], s[T][3]));
    }
    mA = fmaxf(mA, __shfl_xor_sync(~0u, mA, 1)); mA = fmaxf(mA, __shfl_xor_sync(~0u, mA, 2));
    mB = fmaxf(mB, __shfl_xor_sync(~0u, mB, 1)); mB = fmaxf(mB, __shfl_xor_sync(~0u, mB, 2));
    float dA = 0.f, dB = 0.f;
#pragma unroll
    for (int T = 0; T < 7; T++) {
        s[T][0] = __expf(s[T][0] - mA); s[T][1] = __expf(s[T][1] - mA);
        s[T][2] = __expf(s[T][2] - mB); s[T][3] = __expf(s[T][3] - mB);
        dA += s[T][0] + s[T][1]; dB += s[T][2] + s[T][3];
    }
    dA += __shfl_xor_sync(~0u, dA, 1); dA += __shfl_xor_sync(~0u, dA, 2);
    dB += __shfl_xor_sync(~0u, dB, 1); dB += __shfl_xor_sync(~0u, dB, 2);
    float iA = 1.f / dA, iB = 1.f / dB;
#pragma unroll
    for (int T = 0; T < 7; T++) {
        int j0 = T * 8 + 2 * t;
        *(float2*)&amb[rA * 60 + j0] =
            make_float2(tf32f(s[T][0] * iA), tf32f(s[T][1] * iA));
        *(float2*)&amb[(rA + 8) * 60 + j0] =
            make_float2(tf32f(s[T][2] * iB), tf32f(s[T][3] * iB));
    }
    __syncwarp();

    // PV: P frags via ldmatrix, V scalar (transposed access)
    const uint32_t prow = (uint32_t)((w * 16 + l7 + ah * 8) * 240);
    float o[4][4];
#pragma unroll
    for (int nj = 0; nj < 4; nj++) { o[nj][0]=0.f; o[nj][1]=0.f; o[nj][2]=0.f; o[nj][3]=0.f; }
#pragma unroll
    for (int kc = 0; kc < 7; kc++) {
        uint32_t a[4];
        ldsm4(a, ambb + prow + (uint32_t)((2 * kc + bh2) << 4));
        int c = kc * 8 + t;
#pragma unroll
        for (int nj = 0; nj < 4; nj++)
            mma8(o[nj], a, __float_as_uint(vs[c * 40 + nj * 8 + g]),
                 __float_as_uint(vs[(c + 4) * 40 + nj * 8 + g]));
    }
    float* ap = g_att + (size_t)b * 18816 + h * 32;
#pragma unroll
    for (int nj = 0; nj < 4; nj++) {
        int d = nj * 8 + 2 * t;
        if (rA < 49)
            *(float2*)&ap[(size_t)rA * 384 + d] =
                make_float2(tf32f(o[nj][0]), tf32f(o[nj][1]));
        if (rA + 8 < 49)
            *(float2*)&ap[(size_t)(rA + 8) * 384 + d] =
                make_float2(tf32f(o[nj][2]), tf32f(o[nj][3]));
    }
}

// ---------------------------------------------------------------------------
extern "C" void kernel_launch(void* const* d_in, const int* in_sizes, int n_in,
                              void* d_out, int out_size)
{
    const float* hidden = (const float*)d_in[0];
    const float* mask   = (const float*)d_in[1];
    const float* w_qkv  = (const float*)d_in[2];
    const float* b_qkv  = (const float*)d_in[3];
    const float* w_out  = (const float*)d_in[4];
    const float* b_out  = (const float*)d_in[5];
    const float* table  = (const float*)d_in[6];
    float* out = (float*)d_out;

    float* hid_p; cudaGetSymbolAddress((void**)&hid_p, g_hid);
    float* wq_p;  cudaGetSymbolAddress((void**)&wq_p,  g_wq);
    float* wo_p;  cudaGetSymbolAddress((void**)&wo_p,  g_wo);

    prep_kernel<<<(NH4 + NQ4 + NO4 + 255) / 256, 256>>>(
        (const float4*)hidden, (const float4*)w_qkv, (const float4*)w_out,
        (float4*)hid_p, (float4*)wq_p, (float4*)wo_p);

    const int SMEM = 98304;
    cudaFuncSetAttribute(mma_qkv_kernel, cudaFuncAttributeMaxDynamicSharedMemorySize, SMEM);
    cudaFuncSetAttribute(mma_out_kernel, cudaFuncAttributeMaxDynamicSharedMemorySize, SMEM);

    mma_qkv_kernel<<<dim3(9, 784), 256, SMEM>>>(b_qkv);
    attn_kernel<<<24576, 128>>>(mask, table);
    mma_out_kernel<<<dim3(3, 784), 256, SMEM>>>(b_out, out);
}

// round 12
// speedup vs baseline: 1.3917x; 1.2184x over previous
#include <cuda_runtime.h>
#include <math.h>
#include <stdint.h>

#define NROWS 100352

__device__ float g_q[(size_t)24576*1568];   // [B*H, 49, 32], pre-scaled, tf32-rounded
__device__ float g_k[(size_t)24576*1568];
__device__ float g_v[(size_t)24576*1568];
__device__ float g_att[(size_t)NROWS*384];  // tf32-rounded
__device__ float g_hid[(size_t)NROWS*384];  // tf32-rounded hidden
__device__ float g_wq[1152*384];            // tf32-rounded w_qkv
__device__ float g_wo[384*384];             // tf32-rounded w_out
__device__ int   g_pack[2401];              // (i*60+j)<<16 | ridx*12

__device__ __forceinline__ uint32_t smem_u32(const void* p) {
    uint32_t a;
    asm("{ .reg .u64 t; cvta.to.shared.u64 t, %1; cvt.u32.u64 %0, t; }" : "=r"(a) : "l"(p));
    return a;
}
__device__ __forceinline__ uint32_t f2tf(float x) {
    uint32_t r; asm("cvt.rna.tf32.f32 %0, %1;" : "=r"(r) : "f"(x)); return r;
}
__device__ __forceinline__ float tf32f(float x) { return __uint_as_float(f2tf(x)); }
__device__ __forceinline__ void mma8(float* c, const uint32_t* a, uint32_t b0, uint32_t b1) {
    asm volatile("mma.sync.aligned.m16n8k8.row.col.f32.tf32.tf32.f32 "
        "{%0,%1,%2,%3}, {%4,%5,%6,%7}, {%8,%9}, {%0,%1,%2,%3};"
        : "+f"(c[0]), "+f"(c[1]), "+f"(c[2]), "+f"(c[3])
        : "r"(a[0]), "r"(a[1]), "r"(a[2]), "r"(a[3]), "r"(b0), "r"(b1));
}
__device__ __forceinline__ void ldsm4(uint32_t* r, uint32_t a) {
    asm volatile("ldmatrix.sync.aligned.m8n8.x4.shared.b16 {%0,%1,%2,%3}, [%4];"
        : "=r"(r[0]), "=r"(r[1]), "=r"(r[2]), "=r"(r[3]) : "r"(a));
}
__device__ __forceinline__ void ldsm2(uint32_t* r, uint32_t a) {
    asm volatile("ldmatrix.sync.aligned.m8n8.x2.shared.b16 {%0,%1}, [%2];"
        : "=r"(r[0]), "=r"(r[1]) : "r"(a));
}
__device__ __forceinline__ void cp16(uint32_t s, const float* g) {
    asm volatile("cp.async.cg.shared.global [%0], [%1], 16;" :: "r"(s), "l"(g));
}

// ---------------------------------------------------------------------------
// Single prep kernel: tf32-round hidden / w_qkv / w_out + build pack table.
// ---------------------------------------------------------------------------
#define NH4 9633792   // NROWS*384/4
#define NQ4 110592    // 1152*384/4
#define NO4 36864     // 384*384/4

__global__ void prep_kernel(const float4* __restrict__ hid, const float4* __restrict__ wq,
                            const float4* __restrict__ wo, float4* __restrict__ dh,
                            float4* __restrict__ dwq, float4* __restrict__ dwo)
{
    int i = blockIdx.x * blockDim.x + threadIdx.x;
    const float4* s; float4* d; int k;
    if (i < NH4)            { s = hid; d = dh;  k = i; }
    else if (i < NH4 + NQ4) { s = wq;  d = dwq; k = i - NH4; }
    else if (i < NH4 + NQ4 + NO4) { s = wo; d = dwo; k = i - NH4 - NQ4; }
    else return;
    float4 v = s[k];
    v.x = tf32f(v.x); v.y = tf32f(v.y); v.z = tf32f(v.z); v.w = tf32f(v.w);
    d[k] = v;
    if (i < 2401) {
        int r = i / 49, j = i - r * 49;
        int yi = r / 7, xi = r - yi * 7, yj = j / 7, xj = j - yj * 7;
        int ridx = (yi - yj + 6) * 13 + (xi - xj + 6);
        g_pack[i] = ((r * 60 + j) << 16) | (ridx * 12);
    }
}

// ===========================================================================
// TF32 GEMM: C[64x128] of A[M,384] @ W[N,384]^T; inputs pre-rounded.
// 8 warps (2m x 4n), each 32x32 output (acc 32 regs) -> 3 CTAs/SM.
// BK=32, 3-stage cp.async, XOR-swizzled tiles, ldmatrix frag loads.
// smem bytes: A 3x8192 at 0, B 3x16384 at 24576. Total 73728.
// ===========================================================================
__device__ __forceinline__ void gemm_tf32(const float* __restrict__ A,
                                          const float* __restrict__ W,
                                          int bm, int bn, float acc[2][4][4])
{
    extern __shared__ float sm[];
    const int tid = threadIdx.x;
    const int l = tid & 31, l7 = l & 7;
    const int wm = (tid >> 5) >> 2, wn = (tid >> 5) & 3;

    // loader mapping: u -> row = u>>3, c4 = u&7 (16B column units)
    const int rA0 = tid >> 3, c4 = tid & 7;          // A rows 0..31 (s=0), 32..63 (s=1)
    const float* gaA0 = A + (size_t)(bm + rA0) * 384 + c4 * 4;
    const float* gaA1 = gaA0 + (size_t)32 * 384;
    const float* gbB0 = W + (size_t)(bn + rA0) * 384 + c4 * 4;
    const float* gbB1 = gbB0 + (size_t)32 * 384;
    const float* gbB2 = gbB0 + (size_t)64 * 384;
    const float* gbB3 = gbB0 + (size_t)96 * 384;
    const uint32_t smbase = smem_u32(sm);
    const uint32_t sw = (uint32_t)(((c4 ^ rA0) & 7) << 4);
    const uint32_t sAr0 = smbase + (uint32_t)(rA0 * 128) + sw;           // rows 0..31
    const uint32_t sAr1 = sAr0 + 32 * 128;
    const uint32_t sBr0 = smbase + 24576 + (uint32_t)(rA0 * 128) + sw;
    const uint32_t sBr1 = sBr0 + 32 * 128;
    const uint32_t sBr2 = sBr0 + 64 * 128;
    const uint32_t sBr3 = sBr0 + 96 * 128;

#pragma unroll
    for (int mi = 0; mi < 2; mi++)
#pragma unroll
        for (int nj = 0; nj < 4; nj++)
#pragma unroll
            for (int q = 0; q < 4; q++) acc[mi][nj][q] = 0.f;

#define ISSUE(KT) do {                                                        \
    uint32_t oa = (uint32_t)((KT) % 3) * 8192;                                \
    uint32_t ob = (uint32_t)((KT) % 3) * 16384;                               \
    int ko = (KT) * 32;                                                       \
    cp16(sAr0 + oa, gaA0 + ko);  cp16(sAr1 + oa, gaA1 + ko);                  \
    cp16(sBr0 + ob, gbB0 + ko);  cp16(sBr1 + ob, gbB1 + ko);                  \
    cp16(sBr2 + ob, gbB2 + ko);  cp16(sBr3 + ob, gbB3 + ko);                  \
    asm volatile("cp.async.commit_group;" ::: "memory");                      \
} while (0)

    ISSUE(0); ISSUE(1);

    const int ah = (l >> 3) & 1, bh2 = l >> 4;
    uint32_t a_rb[2], b_rb[2];
#pragma unroll
    for (int mi = 0; mi < 2; mi++)
        a_rb[mi] = (uint32_t)((wm * 32 + mi * 16 + l7 + ah * 8) * 128);
#pragma unroll
    for (int p = 0; p < 2; p++)
        b_rb[p] = (uint32_t)((wn * 32 + p * 16 + l7 + bh2 * 8) * 128);

    for (int kt = 0; kt < 12; kt++) {
        if (kt < 11) asm volatile("cp.async.wait_group 1;" ::: "memory");
        else         asm volatile("cp.async.wait_group 0;" ::: "memory");
        __syncthreads();
        if (kt < 10) ISSUE(kt + 2);

        const uint32_t bA = smbase + (uint32_t)(kt % 3) * 8192;
        const uint32_t bB = smbase + 24576 + (uint32_t)(kt % 3) * 16384;
#pragma unroll
        for (int kc = 0; kc < 4; kc++) {
            const uint32_t uA = (uint32_t)(((2 * kc + bh2) ^ l7) << 4);
            const uint32_t uB = (uint32_t)(((2 * kc + ah) ^ l7) << 4);
            uint32_t af0[4], af1[4], b0[4], b1[4];
            ldsm4(af0, bA + a_rb[0] + uA);
            ldsm4(af1, bA + a_rb[1] + uA);
            ldsm4(b0, bB + b_rb[0] + uB);
            ldsm4(b1, bB + b_rb[1] + uB);
            mma8(acc[0][0], af0, b0[0], b0[1]);
            mma8(acc[0][1], af0, b0[2], b0[3]);
            mma8(acc[0][2], af0, b1[0], b1[1]);
            mma8(acc[0][3], af0, b1[2], b1[3]);
            mma8(acc[1][0], af1, b0[0], b0[1]);
            mma8(acc[1][1], af1, b0[2], b0[3]);
            mma8(acc[1][2], af1, b1[0], b1[1]);
            mma8(acc[1][3], af1, b1[2], b1[3]);
        }
    }
#undef ISSUE
}

// ---------------------------------------------------------------------------
__global__ void __launch_bounds__(256, 3)
mma_qkv_kernel(const float* __restrict__ bias)
{
    int tid = threadIdx.x;
    int bm = blockIdx.y * 64, bn = blockIdx.x * 128;
    float acc[2][4][4];
    gemm_tf32(g_hid, g_wq, bm, bn, acc);

    int l = tid & 31;
    int wm = (tid >> 5) >> 2, wn = (tid >> 5) & 3;
    int part = bn / 384;
    int h = ((bn % 384) + wn * 32) >> 5;
    const float scl = (part == 0) ? 0.17677669529663687f : 1.0f;
    float* base = (part == 0) ? g_q : (part == 1) ? g_k : g_v;

#pragma unroll
    for (int mi = 0; mi < 2; mi++)
#pragma unroll
        for (int nj = 0; nj < 4; nj++) {
            int n = bn + wn * 32 + nj * 8 + (l & 3) * 2;
            int d = nj * 8 + (l & 3) * 2;
            float b0 = bias[n], b1 = bias[n + 1];
#pragma unroll
            for (int rh = 0; rh < 2; rh++) {
                int row = bm + wm * 32 + mi * 16 + (l >> 2) + rh * 8;
                int bb = row / 49, ss = row - bb * 49;
                size_t o = (((size_t)(bb * 12 + h) * 49 + ss) << 5) + d;
                *(float2*)&base[o] =
                    make_float2(tf32f((acc[mi][nj][rh*2] + b0) * scl),
                                tf32f((acc[mi][nj][rh*2+1] + b1) * scl));
            }
        }
}

// ---------------------------------------------------------------------------
__global__ void __launch_bounds__(256, 3)
mma_out_kernel(const float* __restrict__ bias, float* __restrict__ C)
{
    int tid = threadIdx.x;
    int bm = blockIdx.y * 64, bn = blockIdx.x * 128;
    float acc[2][4][4];
    gemm_tf32(g_att, g_wo, bm, bn, acc);

    int l = tid & 31;
    int wm = (tid >> 5) >> 2, wn = (tid >> 5) & 3;
#pragma unroll
    for (int mi = 0; mi < 2; mi++)
#pragma unroll
        for (int nj = 0; nj < 4; nj++) {
            int n = bn + wn * 32 + nj * 8 + (l & 3) * 2;
            float b0 = bias[n], b1 = bias[n + 1];
#pragma unroll
            for (int rh = 0; rh < 2; rh++) {
                int row = bm + wm * 32 + mi * 16 + (l >> 2) + rh * 8;
                *(float2*)&C[(size_t)row * 384 + n] =
                    make_float2(acc[mi][nj][rh*2] + b0, acc[mi][nj][rh*2+1] + b1);
            }
        }
}

// ---------------------------------------------------------------------------
// Attention: one CTA per (b,h). ldmatrix fragment loads for Q/K/P.
// (unchanged from R11)
// ---------------------------------------------------------------------------
__global__ void __launch_bounds__(128)
attn_kernel(const float* __restrict__ mask, const float* __restrict__ table)
{
    __shared__ float qs[64 * 36];
    __shared__ float ks[56 * 36];
    __shared__ float vs[56 * 40];
    __shared__ float amb[64 * 60];  // bias+mask, then P (tf32-rounded)

    int bh = blockIdx.x;
    int b = bh / 12, h = bh - b * 12;
    int tid = threadIdx.x, w = tid >> 5, l = tid & 31, g = l >> 2, t = l & 3;
    const int l7 = l & 7, ah = (l >> 3) & 1, bh2 = l >> 4;

    const float4* qg = (const float4*)(g_q + (size_t)bh * 1568);
    const float4* kg = (const float4*)(g_k + (size_t)bh * 1568);
    const float4* vg = (const float4*)(g_v + (size_t)bh * 1568);
    for (int e = tid; e < 392; e += 128) {
        int i = e >> 3, c = (e & 7) * 4;
        *(float4*)&qs[i * 36 + c] = qg[e];
        *(float4*)&ks[i * 36 + c] = kg[e];
        *(float4*)&vs[i * 40 + c] = vg[e];
    }
    for (int e = tid; e < 280; e += 128) vs[1960 + e] = 0.f;
    const float* mrow = mask + (size_t)b * 2401;
    for (int e = tid; e < 2401; e += 128) {
        int pk = g_pack[e];
        amb[pk >> 16] = mrow[e] + table[(pk & 0xFFFF) + h];
    }
    __syncthreads();

    const uint32_t qsb = smem_u32(qs), ksb = smem_u32(ks), ambb = smem_u32(amb);
    const uint32_t qrow = (uint32_t)((w * 16 + l7 + ah * 8) * 144);
    uint32_t krow[3];
#pragma unroll
    for (int p = 0; p < 3; p++)
        krow[p] = (uint32_t)((p * 16 + l7 + bh2 * 8) * 144);
    const uint32_t krow6 = (uint32_t)((48 + l7) * 144);

    // QK^T
    float s[7][4];
#pragma unroll
    for (int T = 0; T < 7; T++) { s[T][0]=0.f; s[T][1]=0.f; s[T][2]=0.f; s[T][3]=0.f; }
    const int rA = w * 16 + g;
#pragma unroll
    for (int kc = 0; kc < 4; kc++) {
        uint32_t a[4];
        ldsm4(a, qsb + qrow + (uint32_t)((2 * kc + bh2) << 4));
        uint32_t uB = (uint32_t)((2 * kc + ah) << 4);
#pragma unroll
        for (int p = 0; p < 3; p++) {
            uint32_t kb[4];
            ldsm4(kb, ksb + krow[p] + uB);
            mma8(s[2*p],   a, kb[0], kb[1]);
            mma8(s[2*p+1], a, kb[2], kb[3]);
        }
        uint32_t k2[2];
        ldsm2(k2, ksb + krow6 + uB);
        mma8(s[6], a, k2[0], k2[1]);
    }
    // + bias + mask, j>=49 -> -inf
#pragma unroll
    for (int T = 0; T < 7; T++) {
        int j0 = T * 8 + 2 * t;
        float2 m0 = *(const float2*)&amb[rA * 60 + j0];
        float2 m1 = *(const float2*)&amb[(rA + 8) * 60 + j0];
        s[T][0] = (j0 < 49)     ? s[T][0] + m0.x : -1e30f;
        s[T][1] = (j0 + 1 < 49) ? s[T][1] + m0.y : -1e30f;
        s[T][2] = (j0 < 49)     ? s[T][2] + m1.x : -1e30f;
        s[T][3] = (j0 + 1 < 49) ? s[T][3] + m1.y : -1e30f;
    }
    // softmax (rows rA, rA+8)
    float mA = -1e30f, mB = -1e30f;
#pragma unroll
    for (int T = 0; T < 7; T++) {
        mA = fmaxf(mA, fmaxf(s[T][0], s[T][1]));
        mB = fmaxf(mB, fmaxf(s[T][2], s[T][3]));
    }
    mA = fmaxf(mA, __shfl_xor_sync(~0u, mA, 1)); mA = fmaxf(mA, __shfl_xor_sync(~0u, mA, 2));
    mB = fmaxf(mB, __shfl_xor_sync(~0u, mB, 1)); mB = fmaxf(mB, __shfl_xor_sync(~0u, mB, 2));
    float dA = 0.f, dB = 0.f;
#pragma unroll
    for (int T = 0; T < 7; T++) {
        s[T][0] = __expf(s[T][0] - mA); s[T][1] = __expf(s[T][1] - mA);
        s[T][2] = __expf(s[T][2] - mB); s[T][3] = __expf(s[T][3] - mB);
        dA += s[T][0] + s[T][1]; dB += s[T][2] + s[T][3];
    }
    dA += __shfl_xor_sync(~0u, dA, 1); dA += __shfl_xor_sync(~0u, dA, 2);
    dB += __shfl_xor_sync(~0u, dB, 1); dB += __shfl_xor_sync(~0u, dB, 2);
    float iA = 1.f / dA, iB = 1.f / dB;
#pragma unroll
    for (int T = 0; T < 7; T++) {
        int j0 = T * 8 + 2 * t;
        *(float2*)&amb[rA * 60 + j0] =
            make_float2(tf32f(s[T][0] * iA), tf32f(s[T][1] * iA));
        *(float2*)&amb[(rA + 8) * 60 + j0] =
            make_float2(tf32f(s[T][2] * iB), tf32f(s[T][3] * iB));
    }
    __syncwarp();

    // PV: P frags via ldmatrix, V scalar (transposed access)
    const uint32_t prow = (uint32_t)((w * 16 + l7 + ah * 8) * 240);
    float o[4][4];
#pragma unroll
    for (int nj = 0; nj < 4; nj++) { o[nj][0]=0.f; o[nj][1]=0.f; o[nj][2]=0.f; o[nj][3]=0.f; }
#pragma unroll
    for (int kc = 0; kc < 7; kc++) {
        uint32_t a[4];
        ldsm4(a, ambb + prow + (uint32_t)((2 * kc + bh2) << 4));
        int c = kc * 8 + t;
#pragma unroll
        for (int nj = 0; nj < 4; nj++)
            mma8(o[nj], a, __float_as_uint(vs[c * 40 + nj * 8 + g]),
                 __float_as_uint(vs[(c + 4) * 40 + nj * 8 + g]));
    }
    float* ap = g_att + (size_t)b * 18816 + h * 32;
#pragma unroll
    for (int nj = 0; nj < 4; nj++) {
        int d = nj * 8 + 2 * t;
        if (rA < 49)
            *(float2*)&ap[(size_t)rA * 384 + d] =
                make_float2(tf32f(o[nj][0]), tf32f(o[nj][1]));
        if (rA + 8 < 49)
            *(float2*)&ap[(size_t)(rA + 8) * 384 + d] =
                make_float2(tf32f(o[nj][2]), tf32f(o[nj][3]));
    }
}

// ---------------------------------------------------------------------------
extern "C" void kernel_launch(void* const* d_in, const int* in_sizes, int n_in,
                              void* d_out, int out_size)
{
    const float* hidden = (const float*)d_in[0];
    const float* mask   = (const float*)d_in[1];
    const float* w_qkv  = (const float*)d_in[2];
    const float* b_qkv  = (const float*)d_in[3];
    const float* w_out  = (const float*)d_in[4];
    const float* b_out  = (const float*)d_in[5];
    const float* table  = (const float*)d_in[6];
    float* out = (float*)d_out;

    float* hid_p; cudaGetSymbolAddress((void**)&hid_p, g_hid);
    float* wq_p;  cudaGetSymbolAddress((void**)&wq_p,  g_wq);
    float* wo_p;  cudaGetSymbolAddress((void**)&wo_p,  g_wo);

    prep_kernel<<<(NH4 + NQ4 + NO4 + 255) / 256, 256>>>(
        (const float4*)hidden, (const float4*)w_qkv, (const float4*)w_out,
        (float4*)hid_p, (float4*)wq_p, (float4*)wo_p);

    const int SMEM = 73728;
    cudaFuncSetAttribute(mma_qkv_kernel, cudaFuncAttributeMaxDynamicSharedMemorySize, SMEM);
    cudaFuncSetAttribute(mma_out_kernel, cudaFuncAttributeMaxDynamicSharedMemorySize, SMEM);

    mma_qkv_kernel<<<dim3(9, 1568), 256, SMEM>>>(b_qkv);
    attn_kernel<<<24576, 128>>>(mask, table);
    mma_out_kernel<<<dim3(3, 1568), 256, SMEM>>>(b_out, out);
}